// round 11
// baseline (speedup 1.0000x reference)
#include <cuda_runtime.h>
#include <cuda_fp16.h>
#include <math.h>
#include <stdint.h>

#define N_PIX   131072

// Output layout offsets (flattened tuple, float32) — total 8651778
#define QUANT_OFF 0
#define LOSS_OFF  8388608
#define PERP_OFF  8388609
#define IDX_OFF   8388610
#define NCS_OFF   8519682
#define NEMA_OFF  8520706
#define NEMB_OFF  8586242

// Scratch (device globals; no allocation allowed)
__device__ int   g_idx[N_PIX];
__device__ float g_esqh[1024];                       // -0.5*||e||^2
__device__ float g_counts[1024];
__device__ float g_dwp[8 * 65536];                   // 8-way privatized dw
__device__ float g_scl[1024];
__device__ float g_loss;
__device__ float g_maxne;                            // max_k ||e_k||
// packed fp16-hi codebook: [chunk 16][kstep 4][n 64][j 8] half2
__device__ __align__(128) __half g_Bpk[16 * 4096];
__device__ __align__(16) int g_cand[N_PIX * 4];      // top-4 candidates (-1 = resolved)
__device__ int   g_fb_list[N_PIX];
__device__ int   g_fb_count;
__device__ int   g_fb_take;

// ---------------------------------------------------------------------------
// helpers (base PTX only)
// ---------------------------------------------------------------------------
__device__ __forceinline__ uint32_t smem_u32(const void* p) {
    uint32_t a;
    asm("{ .reg .u64 t; cvta.to.shared.u64 t, %1; cvt.u32.u64 %0, t; }" : "=r"(a) : "l"(p));
    return a;
}
__device__ __forceinline__ void mma16(float& d0, float& d1, float& d2, float& d3,
                                      const uint32_t* a, uint32_t b0, uint32_t b1) {
    asm volatile(
        "mma.sync.aligned.m16n8k16.row.col.f32.f16.f16.f32 "
        "{%0,%1,%2,%3}, {%4,%5,%6,%7}, {%8,%9}, {%0,%1,%2,%3};"
        : "+f"(d0), "+f"(d1), "+f"(d2), "+f"(d3)
        : "r"(a[0]), "r"(a[1]), "r"(a[2]), "r"(a[3]), "r"(b0), "r"(b1));
}
#define CP_ASYNC16(dst, src) \
    asm volatile("cp.async.cg.shared.global [%0], [%1], 16;" :: "r"(dst), "l"(src) : "memory")
#define CP_COMMIT() asm volatile("cp.async.commit_group;" ::: "memory")
#define CP_WAIT1()  asm volatile("cp.async.wait_group 1;" ::: "memory")
#define CP_WAIT0()  asm volatile("cp.async.wait_group 0;" ::: "memory")

__device__ __forceinline__ void red_v4(float* p, float a, float b, float c, float d) {
    asm volatile("red.global.add.v4.f32 [%0], {%1,%2,%3,%4};"
                 :: "l"(p), "f"(a), "f"(b), "f"(c), "f"(d) : "memory");
}
__device__ __forceinline__ uint32_t packh2(float x0, float x1) {
    __half2 hh = __halves2half2(__float2half_rn(x0), __float2half_rn(x1));
    return *(uint32_t*)&hh;
}
// top-4 insertion (strict >: earlier/lower index kept on ties; codes ascend)
__device__ __forceinline__ void top4(float* b, int* bi, float s, int idx) {
    if (s <= b[3]) return;
    if (s > b[0])      { b[3]=b[2];bi[3]=bi[2]; b[2]=b[1];bi[2]=bi[1]; b[1]=b[0];bi[1]=bi[0]; b[0]=s;bi[0]=idx; }
    else if (s > b[1]) { b[3]=b[2];bi[3]=bi[2]; b[2]=b[1];bi[2]=bi[1]; b[1]=s;bi[1]=idx; }
    else if (s > b[2]) { b[3]=b[2];bi[3]=bi[2]; b[2]=s;bi[2]=idx; }
    else               { b[3]=s;bi[3]=idx; }
}

// ---------------------------------------------------------------------------
// Kernel 1: prep — fp16-hi packed codebook, esqh, zero accumulators
// grid 1024 (code k), 64 threads (channel d)
// ---------------------------------------------------------------------------
__global__ void prep_kernel(const float* __restrict__ embed) {
    int k = blockIdx.x;
    int t = threadIdx.x;
    float v = embed[k * 64 + t];
    #pragma unroll
    for (int i = 0; i < 8; i++) g_dwp[i * 65536 + k * 64 + t] = 0.0f;

    // pack layout: halves index = chunk*4096 + (s*64+n)*16 + j*2 + h
    // pair p covers k_local = 2p, 2p+1 within s-group; j order {0,4,1,5,2,6,3,7}
    int c = k >> 6, n = k & 63, s = t >> 4, dl = t & 15, p = dl >> 1, h = dl & 1;
    int j = ((p & 3) << 1) | (p >> 2);
    g_Bpk[c * 4096 + (s * 64 + n) * 16 + j * 2 + h] = __float2half_rn(v);

    float sq = v * v;
    #pragma unroll
    for (int o = 16; o; o >>= 1) sq += __shfl_down_sync(0xffffffffu, sq, o);
    __shared__ float sm[2];
    if ((t & 31) == 0) sm[t >> 5] = sq;
    __syncthreads();
    if (t == 0) {
        g_esqh[k] = -0.5f * (sm[0] + sm[1]);
        g_counts[k] = 0.0f;
        if (k == 0) g_loss = 0.0f;
    }
}

// ---------------------------------------------------------------------------
// Kernel 1b: max_k ||e_k|| (reads esqh = -0.5||e||^2)
// ---------------------------------------------------------------------------
__global__ void maxk_kernel() {
    __shared__ float sm[1024];
    int t = threadIdx.x;
    sm[t] = g_esqh[t];
    __syncthreads();
    for (int o = 512; o; o >>= 1) {
        if (t < o) sm[t] = fminf(sm[t], sm[t + o]);
        __syncthreads();
    }
    if (t == 0) g_maxne = sqrtf(-2.0f * sm[0]);
}

// ---------------------------------------------------------------------------
// Kernel 1c: reset fallback counters (also aligns argmin to profile slot 3)
// ---------------------------------------------------------------------------
__global__ void reset_kernel() {
    g_fb_count = 0;
    g_fb_take = 0;
}

// ---------------------------------------------------------------------------
// Kernel 2: hh-only fp16 argmin via mma.sync m16n8k16 (f32 accum — EXACT
// products, only dropped cross/lo terms bounded by E per pixel).
// 1024 blocks x 256 threads; block = 128 pixels; codes in 16 chunks of 64.
// Emits: certain g_idx, or top-4 candidate list, or full-fallback entry.
// ---------------------------------------------------------------------------
__global__ void __launch_bounds__(256) argmin_mma(const float* __restrict__ in,
                                                  float* __restrict__ out) {
    __shared__ __align__(16) __half Bsm[8192];    // 2 bufs x 8KB; reused for merge
    __shared__ float esqs[1024];                  // later [0..127] = per-pixel ||x||^2
    uint32_t smb = smem_u32(Bsm);

    const int tid = threadIdx.x;
    const int w   = tid >> 5;
    const int ln  = tid & 31;
    const int g   = ln >> 2;
    const int t   = ln & 3;
    const int p0  = blockIdx.x * 128;
    const int bimg = p0 >> 12;
    const int hw0  = p0 & 4095;

    // chunk 0 -> buf 0 (8KB = 512 x 16B)
    #pragma unroll
    for (int jj = 0; jj < 2; jj++) {
        int idx = tid + jj * 256;
        CP_ASYNC16(smb + idx * 16, (const char*)g_Bpk + idx * 16);
    }
    CP_COMMIT();

    #pragma unroll
    for (int i = 0; i < 4; i++) esqs[tid + i * 256] = g_esqh[tid + i * 256];

    // A fragments: 16 pixels x 64 ch in fp16-hi; per-pixel sumsq on the side
    uint32_t ah[4][4];
    float ssa = 0.0f, ssb = 0.0f;
    {
        const float* ap = in + (size_t)bimg * 262144 + hw0 + w * 16 + g;
        #pragma unroll
        for (int s = 0; s < 4; s++) {
            int d0 = 16 * s + 2 * t;
            float xa0 = ap[d0 * 4096],           xa1 = ap[(d0 + 1) * 4096];
            float xb0 = ap[d0 * 4096 + 8],       xb1 = ap[(d0 + 1) * 4096 + 8];
            float ya0 = ap[(d0 + 8) * 4096],     ya1 = ap[(d0 + 9) * 4096];
            float yb0 = ap[(d0 + 8) * 4096 + 8], yb1 = ap[(d0 + 9) * 4096 + 8];
            ah[s][0] = packh2(xa0, xa1);
            ah[s][1] = packh2(xb0, xb1);
            ah[s][2] = packh2(ya0, ya1);
            ah[s][3] = packh2(yb0, yb1);
            ssa += xa0 * xa0 + xa1 * xa1 + ya0 * ya0 + ya1 * ya1;
            ssb += xb0 * xb0 + xb1 * xb1 + yb0 * yb0 + yb1 * yb1;
        }
        // reduce over the 4 t-lanes (lanes g*4+t)
        ssa += __shfl_xor_sync(0xffffffffu, ssa, 1);
        ssa += __shfl_xor_sync(0xffffffffu, ssa, 2);
        ssb += __shfl_xor_sync(0xffffffffu, ssb, 1);
        ssb += __shfl_xor_sync(0xffffffffu, ssb, 2);
    }

    float ba[4]  = {-3.4e38f, -3.4e38f, -3.4e38f, -3.4e38f};
    float bbv[4] = {-3.4e38f, -3.4e38f, -3.4e38f, -3.4e38f};
    int   bia[4] = {0, 0, 0, 0}, bib[4] = {0, 0, 0, 0};

    for (int c = 0; c < 16; c++) {
        const int buf = c & 1;
        if (c < 15) {
            int nb = (c + 1) & 1;
            #pragma unroll
            for (int jj = 0; jj < 2; jj++) {
                int idx = tid + jj * 256;
                CP_ASYNC16(smb + nb * 8192 + idx * 16,
                           (const char*)g_Bpk + (c + 1) * 8192 + idx * 16);
            }
            CP_COMMIT();
            CP_WAIT1();
        } else {
            CP_WAIT0();
        }
        __syncthreads();

        const uint32_t bb = smb + buf * 8192;
        const int kbase = c * 64;

        #pragma unroll
        for (int nt = 0; nt < 8; nt++) {
            float c0 = 0.f, c1 = 0.f, c2 = 0.f, c3 = 0.f;
            const int nb_ = nt * 8 + g;
            #pragma unroll
            for (int s = 0; s < 4; s++) {
                uint32_t offh = bb + (s * 64 + nb_) * 32 + 8 * t;
                uint32_t bh0, bh1;
                asm volatile("ld.shared.v2.b32 {%0,%1}, [%2];" : "=r"(bh0), "=r"(bh1) : "r"(offh));
                mma16(c0, c1, c2, c3, ah[s], bh0, bh1);
            }
            int code0 = kbase + nt * 8 + 2 * t;
            float e0 = esqs[code0], e1 = esqs[code0 + 1];
            top4(ba,  bia, c0 + e0, code0);
            top4(ba,  bia, c1 + e1, code0 + 1);
            top4(bbv, bib, c2 + e0, code0);
            top4(bbv, bib, c3 + e1, code0 + 1);
        }
        __syncthreads();
    }

    // ---- merge phase: write per-lane top4 + sumsq into smem, 1 thread/pixel
    float2* cands = (float2*)Bsm;          // [128][16] (val, idx-bits) = 16KB
    int pa = w * 16 + g;                   // pixel slot for row g
    int pb = pa + 8;                       // pixel slot for row g+8
    #pragma unroll
    for (int q = 0; q < 4; q++) {
        cands[pa * 16 + t * 4 + q] = make_float2(ba[q],  __int_as_float(bia[q]));
        cands[pb * 16 + t * 4 + q] = make_float2(bbv[q], __int_as_float(bib[q]));
    }
    if (t == 0) { esqs[pa] = ssa; esqs[pb] = ssb; }
    __syncthreads();

    if (tid < 128) {
        float mb[4] = {-3.4e38f, -3.4e38f, -3.4e38f, -3.4e38f};
        int   mi[4] = {0, 0, 0, 0};
        #pragma unroll
        for (int q = 0; q < 16; q++) {
            float2 cv = cands[tid * 16 + q];
            top4(mb, mi, cv.x, __float_as_int(cv.y));
        }
        float E = 1.05e-3f * sqrtf(esqs[tid]) * g_maxne + 1.5e-3f;
        float thr = mb[0] - 2.0f * E;
        int n = p0 + tid;
        if (mb[3] >= thr) {
            // >=4 plausible winners -> exact full fallback
            g_cand[4 * n] = -1;
            g_fb_list[atomicAdd(&g_fb_count, 1)] = n;
        } else if (mb[1] < thr) {
            // certain winner
            g_idx[n] = mi[0];
            out[IDX_OFF + n] = (float)mi[0];
            g_cand[4 * n] = -1;
        } else {
            int4 cc = make_int4(mi[0], mi[1], mi[2], mi[3]);
            *(int4*)(g_cand + 4 * n) = cc;
        }
    }
}

// ---------------------------------------------------------------------------
// Kernel 2b: exact fp32 recheck of the <=4 candidates per uncertain pixel
// ---------------------------------------------------------------------------
__global__ void recheck_kernel(const float* __restrict__ in,
                               const float* __restrict__ embed,
                               float* __restrict__ out) {
    int n = blockIdx.x * 256 + threadIdx.x;
    int4 c = *(const int4*)(g_cand + 4 * n);
    if (c.x < 0) return;
    const float* xp = in + (size_t)(n >> 12) * 262144 + (n & 4095);
    const float4* e0 = (const float4*)(embed + c.x * 64);
    const float4* e1 = (const float4*)(embed + c.y * 64);
    const float4* e2 = (const float4*)(embed + c.z * 64);
    const float4* e3 = (const float4*)(embed + c.w * 64);
    float s0 = g_esqh[c.x], s1 = g_esqh[c.y], s2 = g_esqh[c.z], s3 = g_esqh[c.w];
    #pragma unroll
    for (int j = 0; j < 16; j++) {
        float4 v0 = __ldg(e0 + j), v1 = __ldg(e1 + j), v2 = __ldg(e2 + j), v3 = __ldg(e3 + j);
        int d = j * 4;
        float x0 = xp[(size_t)d * 4096];
        float x1 = xp[(size_t)(d + 1) * 4096];
        float x2 = xp[(size_t)(d + 2) * 4096];
        float x3 = xp[(size_t)(d + 3) * 4096];
        s0 = fmaf(x0, v0.x, s0); s0 = fmaf(x1, v0.y, s0); s0 = fmaf(x2, v0.z, s0); s0 = fmaf(x3, v0.w, s0);
        s1 = fmaf(x0, v1.x, s1); s1 = fmaf(x1, v1.y, s1); s1 = fmaf(x2, v1.z, s1); s1 = fmaf(x3, v1.w, s1);
        s2 = fmaf(x0, v2.x, s2); s2 = fmaf(x1, v2.y, s2); s2 = fmaf(x2, v2.z, s2); s2 = fmaf(x3, v2.w, s2);
        s3 = fmaf(x0, v3.x, s3); s3 = fmaf(x1, v3.y, s3); s3 = fmaf(x2, v3.z, s3); s3 = fmaf(x3, v3.w, s3);
    }
    float bv = s0; int bi = c.x;
    if (s1 > bv || (s1 == bv && c.y < bi)) { bv = s1; bi = c.y; }
    if (s2 > bv || (s2 == bv && c.z < bi)) { bv = s2; bi = c.z; }
    if (s3 > bv || (s3 == bv && c.w < bi)) { bv = s3; bi = c.w; }
    g_idx[n] = bi;
    out[IDX_OFF + n] = (float)bi;
}

// ---------------------------------------------------------------------------
// Kernel 2c: exact fp32 full fallback for ambiguous pixels (rare)
// ---------------------------------------------------------------------------
__global__ void fb_kernel(const float* __restrict__ in,
                          const float* __restrict__ embed,
                          float* __restrict__ out) {
    __shared__ float xs[64];
    __shared__ float rv[256];
    __shared__ int   ri[256];
    __shared__ int   cur;
    while (true) {
        if (threadIdx.x == 0) cur = atomicAdd(&g_fb_take, 1);
        __syncthreads();
        int i = cur;
        if (i >= g_fb_count) break;
        int n = g_fb_list[i];
        int b = n >> 12, hw = n & 4095;
        if (threadIdx.x < 64)
            xs[threadIdx.x] = in[(size_t)b * 262144 + threadIdx.x * 4096 + hw];
        __syncthreads();

        int k0 = threadIdx.x * 4;
        float bv = -3.4e38f; int bi = 0;
        for (int k = k0; k < k0 + 4; k++) {
            const float* e = embed + k * 64;
            float s = g_esqh[k];
            #pragma unroll
            for (int c = 0; c < 64; c++) s = fmaf(xs[c], e[c], s);
            if (s > bv) { bv = s; bi = k; }
        }
        rv[threadIdx.x] = bv; ri[threadIdx.x] = bi;
        __syncthreads();
        for (int o = 128; o; o >>= 1) {
            if (threadIdx.x < o) {
                float v2 = rv[threadIdx.x + o]; int i2 = ri[threadIdx.x + o];
                if (v2 > rv[threadIdx.x] || (v2 == rv[threadIdx.x] && i2 < ri[threadIdx.x])) {
                    rv[threadIdx.x] = v2; ri[threadIdx.x] = i2;
                }
            }
            __syncthreads();
        }
        if (threadIdx.x == 0) { g_idx[n] = ri[0]; out[IDX_OFF + n] = (float)ri[0]; }
        __syncthreads();
    }
}

// ---------------------------------------------------------------------------
// Kernel 3: quantize — one thread per pixel; contiguous embed-row gather,
// coalesced channel-strided in/out, privatized v4 vector reductions for dw.
// ---------------------------------------------------------------------------
__global__ void quant_kernel(const float* __restrict__ in,
                             const float* __restrict__ embed,
                             float* __restrict__ out) {
    int n = blockIdx.x * 256 + threadIdx.x;       // pixel 0..131071
    int b = n >> 12, hw = n & 4095;
    int r = g_idx[n];

    const float4* er = (const float4*)(embed + r * 64);
    const float* ib = in + (size_t)b * 262144 + hw;
    float* ob = out + QUANT_OFF + (size_t)b * 262144 + hw;
    float* dwr = g_dwp + (blockIdx.x & 7) * 65536 + r * 64;

    float s = 0.0f;
    #pragma unroll
    for (int j = 0; j < 16; j++) {
        float4 q = __ldg(er + j);
        int d = j * 4;
        float x0 = ib[(size_t)d * 4096];
        float x1 = ib[(size_t)(d + 1) * 4096];
        float x2 = ib[(size_t)(d + 2) * 4096];
        float x3 = ib[(size_t)(d + 3) * 4096];
        ob[(size_t)d * 4096]       = q.x;
        ob[(size_t)(d + 1) * 4096] = q.y;
        ob[(size_t)(d + 2) * 4096] = q.z;
        ob[(size_t)(d + 3) * 4096] = q.w;
        float e0 = q.x - x0, e1 = q.y - x1, e2 = q.z - x2, e3 = q.w - x3;
        s += e0 * e0 + e1 * e1 + e2 * e2 + e3 * e3;
        red_v4(dwr + d, x0, x1, x2, x3);
    }
    atomicAdd(&g_counts[r], 1.0f);

    #pragma unroll
    for (int o = 16; o; o >>= 1) s += __shfl_down_sync(0xffffffffu, s, o);
    __shared__ float sm[8];
    if ((threadIdx.x & 31) == 0) sm[threadIdx.x >> 5] = s;
    __syncthreads();
    if (threadIdx.x == 0) {
        float tot = 0.0f;
        #pragma unroll
        for (int i = 0; i < 8; i++) tot += sm[i];
        atomicAdd(&g_loss, tot);
    }
}

// ---------------------------------------------------------------------------
// Kernel 4a: scalars
// ---------------------------------------------------------------------------
__global__ void scalar_kernel(const float* __restrict__ ema_cs, float* __restrict__ out) {
    __shared__ float s1[1024];
    __shared__ float s2[1024];
    int k = threadIdx.x;
    float cnt = g_counts[k];
    float ncs = 0.99f * ema_cs[k] + 0.01f * cnt;
    out[NCS_OFF + k] = ncs;
    float p = cnt * (1.0f / 131072.0f);
    s1[k] = ncs;
    s2[k] = p * logf(p + 1e-10f);
    __syncthreads();
    for (int o = 512; o; o >>= 1) {
        if (k < o) { s1[k] += s1[k + o]; s2[k] += s2[k + o]; }
        __syncthreads();
    }
    float nsum = s1[0];
    float csz = (ncs + 1e-5f) / (nsum + 1024.0f * 1e-5f) * nsum;
    g_scl[k] = fmaxf(csz, 1e-5f);
    if (k == 0) {
        out[LOSS_OFF] = 0.25f * g_loss * (1.0f / 8388608.0f);
        out[PERP_OFF] = expf(-s2[0]);
    }
}

// ---------------------------------------------------------------------------
// Kernel 4b: wide EMA update (sums the 8 dw replicas)
// ---------------------------------------------------------------------------
__global__ void ema_kernel(const float* __restrict__ ema_w, float* __restrict__ out) {
    int e = blockIdx.x * 512 + threadIdx.x;       // 0..65535
    int kk = e >> 6;
    float dw = 0.0f;
    #pragma unroll
    for (int i = 0; i < 8; i++) dw += g_dwp[i * 65536 + e];
    float w = 0.99f * ema_w[e] + 0.01f * dw;
    out[NEMA_OFF + e] = w;
    out[NEMB_OFF + e] = w / g_scl[kk];
}

// ---------------------------------------------------------------------------
extern "C" void kernel_launch(void* const* d_in, const int* in_sizes, int n_in,
                              void* d_out, int out_size) {
    const float* in    = (const float*)d_in[0];
    const float* embed = (const float*)d_in[1];
    const float* ecs   = (const float*)d_in[2];
    const float* emw   = (const float*)d_in[3];
    float* out = (float*)d_out;

    prep_kernel<<<1024, 64>>>(embed);          // launch 0
    maxk_kernel<<<1, 1024>>>();                // launch 1
    reset_kernel<<<1, 1>>>();                  // launch 2
    argmin_mma<<<1024, 256>>>(in, out);        // launch 3 (profiled slot)
    recheck_kernel<<<512, 256>>>(in, embed, out);
    fb_kernel<<<296, 256>>>(in, embed, out);
    quant_kernel<<<512, 256>>>(in, embed, out);
    scalar_kernel<<<1, 1024>>>(ecs, out);
    ema_kernel<<<128, 512>>>(emw, out);
}